// round 17
// baseline (speedup 1.0000x reference)
#include <cuda_runtime.h>
#include <math.h>

#define B_   16
#define N_   2048
#define K_   16
#define EPS_ 1e-8f

#define G_   16                 // grid cells per side
#define NC_  (G_ * G_)          // 256 cells
#define H_   (1.0f / 16.0f)     // cell size

// Output layout (tuple flattened in order):
//   psi_prime : B*N*2  floats  @ 0
//   features  : B*N*5  floats  @ 65536
//   knn_idx   : B*N*16 floats  @ 229376
#define PSI_OFF  0
#define FEAT_OFF (B_ * N_ * 2)
#define KNN_OFF  (B_ * N_ * 2 + B_ * N_ * 5)

typedef unsigned long long u64;
typedef unsigned int u32;

#define SENT 0xFFFFFFFFFFFFFFFFull

// Cell-sorted candidate data {x, y, sq, j_as_bits} + per-batch cell offsets.
__device__ float4 g_sorted[B_ * N_];
__device__ int    g_cellStart[B_][NC_ + 1];

__device__ __forceinline__ int cell_of(float v) {
    int c = (int)(v * (float)G_);
    return c < 0 ? 0 : (c > G_ - 1 ? G_ - 1 : c);
}

// ---------------------------------------------------------------------------
// Kernel 1: features + encoder (tiny MLP). Unchanged math; no scratch here.
// ---------------------------------------------------------------------------
__global__ void encode_kernel(const float* __restrict__ coords,
                              const float* __restrict__ demands,
                              const float* __restrict__ capacity,
                              const float* __restrict__ Wa,
                              const float* __restrict__ ba,
                              const float* __restrict__ W1,
                              const float* __restrict__ b1,
                              const float* __restrict__ W2,
                              const float* __restrict__ b2,
                              float* __restrict__ out)
{
    int b = blockIdx.y;
    int n = blockIdx.x * blockDim.x + threadIdx.x;
    if (n >= N_) return;

    __shared__ float sWa[10], sba[2], sW1[80], sb1[16], sW2[16], sb2_s;
    int t = threadIdx.x;
    if (t < 10) sWa[t] = Wa[t];
    if (t < 2)  sba[t] = ba[t];
    if (t < 80) sW1[t] = W1[t];
    if (t < 16) { sb1[t] = b1[t]; sW2[t] = W2[t]; }
    if (t == 0) sb2_s = b2[0];
    __syncthreads();

    const float* cp = coords + ((long long)b * N_ + n) * 2;
    float x = cp[0], y = cp[1];

    float dx0 = coords[(long long)b * N_ * 2 + 0];
    float dy0 = coords[(long long)b * N_ * 2 + 1];
    float rx = x - dx0, ry = y - dy0;
    float dist = sqrtf(rx * rx + ry * ry + EPS_);
    float ang  = atan2f(ry, rx);
    float dem  = demands[(long long)b * N_ + n] / capacity[b];

    float f0 = x, f1 = y, f2 = dem, f3 = dist, f4 = ang;

    float* fo = out + FEAT_OFF + ((long long)b * N_ + n) * 5;
    fo[0] = f0; fo[1] = f1; fo[2] = f2; fo[3] = f3; fo[4] = f4;

    float p0 = sba[0] + f0*sWa[0] + f1*sWa[1] + f2*sWa[2] + f3*sWa[3] + f4*sWa[4];
    float p1 = sba[1] + f0*sWa[5] + f1*sWa[6] + f2*sWa[7] + f3*sWa[8] + f4*sWa[9];
    float nrm = sqrtf(p0 * p0 + p1 * p1);
    float inv = 1.0f / (nrm + EPS_);
    p0 *= inv; p1 *= inv;

    float theta = sb2_s;
    #pragma unroll
    for (int h = 0; h < 16; ++h) {
        const float* w = sW1 + h * 5;
        float a = sb1[h] + f0*w[0] + f1*w[1] + f2*w[2] + f3*w[3] + f4*w[4];
        theta += tanhf(a) * sW2[h];
    }
    float c = cosf(theta), s = sinf(theta);

    float* po = out + PSI_OFF + ((long long)b * N_ + n) * 2;
    po[0] = c * p0 - s * p1;
    po[1] = s * p0 + c * p1;
}

// ---------------------------------------------------------------------------
// Kernel 2: grid build. One block per batch: count -> scan -> scatter.
// sq = rn(rn(x*x) + rn(y*y)) (reference rounding). Within-cell scatter order
// is atomic-nondeterministic but irrelevant: selection uses total-order keys.
// ---------------------------------------------------------------------------
__global__ void build_kernel(const float* __restrict__ coords)
{
    int b = blockIdx.x;
    __shared__ int scnt[NC_], soff[NC_ + 1];
    int t = threadIdx.x;   // 256 threads

    scnt[t] = 0;
    __syncthreads();

    const float* cb = coords + (long long)b * N_ * 2;
    for (int i = t; i < N_; i += 256) {
        float x = cb[2 * i], y = cb[2 * i + 1];
        atomicAdd(&scnt[cell_of(y) * G_ + cell_of(x)], 1);
    }
    __syncthreads();

    if (t == 0) {
        int acc = 0;
        for (int c = 0; c < NC_; ++c) { soff[c] = acc; acc += scnt[c]; }
        soff[NC_] = acc;
    }
    __syncthreads();

    g_cellStart[b][t] = soff[t];
    if (t == 0) g_cellStart[b][NC_] = N_;

    scnt[t] = 0;     // reuse as per-cell cursor
    __syncthreads();

    for (int i = t; i < N_; i += 256) {
        float x = cb[2 * i], y = cb[2 * i + 1];
        int c = cell_of(y) * G_ + cell_of(x);
        float sq = __fadd_rn(__fmul_rn(x, x), __fmul_rn(y, y));
        int pos = soff[c] + atomicAdd(&scnt[c], 1);
        g_sorted[(long long)b * N_ + pos] =
            make_float4(x, y, sq, __uint_as_float((u32)i));
    }
}

// ---------------------------------------------------------------------------
// KNN helpers
// ---------------------------------------------------------------------------

// Monotone map: float bits -> u32 whose unsigned order == float order.
__device__ __forceinline__ u32 fmap(u32 b) {
    return b ^ ((u32)((int)b >> 31) | 0x80000000u);
}

// d2 bit-exact with the reference:
//   t = rn(xq*xj); dot = fma(yq,yj,t); s = rn(sqq+sqj)
//   ref rn(s - rn(2*dot)) == rn(s - 2*dot) == fma(-2, dot, s)   [2*dot exact]
#define D2_OF(xv, yv, sv) \
    __fmaf_rn(-2.0f, __fmaf_rn(yq, (yv), __fmul_rn(xq, (xv))), \
              __fadd_rn(sqq, (sv)))

// Stable insert of a total-order u64 key into ascending L[16]. If the key
// >= L[15] it is a provable no-op. Keys unique (j unique) -> exact top_k
// order including ties (fmap(d2) major, j minor).
#define INSERT_U64(keyv)                                     \
    do {                                                     \
        u64 kv = (keyv);                                     \
        _Pragma("unroll")                                    \
        for (int k = 15; k > 0; --k) {                       \
            bool shift = kv < L[k - 1];                      \
            u64 sv = shift ? L[k - 1] : kv;                  \
            bool place = kv < L[k];                          \
            L[k] = place ? sv : L[k];                        \
        }                                                    \
        if (kv < L[0]) L[0] = kv;                            \
    } while (0)

// ---------------------------------------------------------------------------
// Kernel 3: grid KNN. One thread per CELL-SORTED query position, so a warp's
// 32 queries sit in adjacent cells and the whole warp walks the SAME cells:
// every candidate load is one broadcast LDG.128. Expanding square from the
// warp's cell bbox; per-lane geometric stop with a conservative margin.
// ---------------------------------------------------------------------------
__global__ void __launch_bounds__(64)
knn_kernel(float* __restrict__ out_knn)
{
    int gt = blockIdx.x * 64 + threadIdx.x;   // 0 .. B*N-1
    int b  = gt >> 11;
    int t  = gt & (N_ - 1);                   // sorted position in batch

    const float4* pk = g_sorted + (long long)b * N_;
    const int*    cs = g_cellStart[b];

    float4 me = pk[t];
    float xq = me.x, yq = me.y, sqq = me.z;
    u32 qj = __float_as_uint(me.w);

    int cx = cell_of(xq), cy = cell_of(yq);

    // warp bbox of cells (5-step shfl reductions)
    int cx0 = cx, cx1 = cx, cy0 = cy, cy1 = cy;
    #pragma unroll
    for (int s = 1; s < 32; s <<= 1) {
        cx0 = min(cx0, __shfl_xor_sync(0xffffffffu, cx0, s));
        cx1 = max(cx1, __shfl_xor_sync(0xffffffffu, cx1, s));
        cy0 = min(cy0, __shfl_xor_sync(0xffffffffu, cy0, s));
        cy1 = max(cy1, __shfl_xor_sync(0xffffffffu, cy1, s));
    }

    u64 L[16];
    #pragma unroll
    for (int k = 0; k < 16; ++k) L[k] = SENT;
    float bd15f = 3.4e38f;      // d2 of current 16th (shadow; inf until full)

    int pX0 = 1, pX1 = 0, pY0 = 1, pY1 = 0;   // empty previous box

    for (int d = 0; ; ++d) {
        int X0 = max(0, cx0 - d), X1 = min(G_ - 1, cx1 + d);
        int Y0 = max(0, cy0 - d), Y1 = min(G_ - 1, cy1 + d);

        for (int yy = Y0; yy <= Y1; ++yy) {
            for (int xx = X0; xx <= X1; ++xx) {
                if (xx >= pX0 && xx <= pX1 && yy >= pY0 && yy <= pY1)
                    continue;   // already processed
                int c = yy * G_ + xx;
                int s = cs[c], e = cs[c + 1];
                for (int idx = s; idx < e; ++idx) {
                    float4 cd = pk[idx];            // warp-uniform broadcast
                    float d2 = D2_OF(cd.x, cd.y, cd.z);
                    u32 j2 = __float_as_uint(cd.w);
                    // '<=' so an equal-d2 candidate can still win by
                    // smaller j; INSERT resolves exactly via the u64 key.
                    if (j2 != qj && d2 <= bd15f) {
                        u64 key = ((u64)fmap(__float_as_uint(d2)) << 32) | j2;
                        INSERT_U64(key);
                        u32 hw = (u32)(L[15] >> 32);
                        bd15f = (hw == 0xFFFFFFFFu) ? 3.4e38f
                              : __uint_as_float((hw & 0x80000000u)
                                                ? (hw ^ 0x80000000u) : ~hw);
                    }
                }
            }
        }

        bool full = (X0 == 0) & (X1 == G_ - 1) & (Y0 == 0) & (Y1 == G_ - 1);
        // gap = exact-geometry distance from my point to the unvisited
        // region (domain edges contribute +inf: nothing beyond them).
        float gl = (X0 == 0)      ? 1e30f : (xq - (float)X0 * H_);
        float gr = (X1 == G_ - 1) ? 1e30f : ((float)(X1 + 1) * H_ - xq);
        float gb = (Y0 == 0)      ? 1e30f : (yq - (float)Y0 * H_);
        float gu = (Y1 == G_ - 1) ? 1e30f : ((float)(Y1 + 1) * H_ - yq);
        float gap = fminf(fminf(gl, gr), fminf(gb, gu));
        // margin 1e-5 >> float cancellation error of d2 (~1e-6): any
        // excluded candidate has float-d2 > bd15f strictly -> cannot enter
        // or tie the top-16.
        bool done = full || (bd15f < gap * gap - 1e-5f);
        if (__all_sync(0xffffffffu, done)) break;
        pX0 = X0; pX1 = X1; pY0 = Y0; pY1 = Y1;
    }

    // write my 16 indices to the ORIGINAL query row qj
    float* o = out_knn + ((long long)b * N_ + qj) * K_;
    #pragma unroll
    for (int k = 0; k < K_; ++k)
        o[k] = (float)(u32)(L[k] & 0xFFFFFFFFu);
}

// ---------------------------------------------------------------------------
extern "C" void kernel_launch(void* const* d_in, const int* in_sizes, int n_in,
                              void* d_out, int out_size)
{
    const float* coords   = (const float*)d_in[0];
    const float* demands  = (const float*)d_in[1];
    const float* capacity = (const float*)d_in[2];
    const float* Wa       = (const float*)d_in[3];
    const float* ba       = (const float*)d_in[4];
    const float* W1       = (const float*)d_in[5];
    const float* b1       = (const float*)d_in[6];
    const float* W2       = (const float*)d_in[7];
    const float* b2       = (const float*)d_in[8];
    float* out = (float*)d_out;

    encode_kernel<<<dim3(N_ / 256, B_), 256>>>(coords, demands, capacity,
                                               Wa, ba, W1, b1, W2, b2, out);
    build_kernel<<<B_, 256>>>(coords);
    knn_kernel<<<B_ * N_ / 64, 64>>>(out + KNN_OFF);
}